// round 1
// baseline (speedup 1.0000x reference)
#include <cuda_runtime.h>
#include <math.h>

// ---------------- problem constants ----------------
#define N_RBF   300
#define NBUCK   512
#define N_MAXN  100352            // 784*128
#define E_MAXE  400384            // 3128*128
#define RBF_STEP (30.0f/299.0f)
#define RBF_INV  (299.0f/30.0f)   // 1/gap
#define WIN      2.0f             // |d-c|>2 -> exp(-39.9) ~ 5e-18, negligible

// ---------------- device scratch (static globals; no runtime alloc) ----------------
__device__ float g_h  [(size_t)N_MAXN*128];
__device__ float g_t  [(size_t)E_MAXE*428];
__device__ float g_ee [(size_t)E_MAXE*128];
__device__ float g_tmp[(size_t)E_MAXE*128];
__device__ float g_W1T [3*300*428];
__device__ float g_We2T[3*428*128];
__device__ float g_Wn1T[3*128*128];
__device__ float g_Wn2T[3*128*128];
__device__ float g_WcT [3*128*128];
__device__ float g_Wr1T[128*128];
__device__ float g_P   [3*400*428];
__device__ int   g_perm[E_MAXE];
__device__ int   g_hist[2*NBUCK];

// ---------------- small utility kernels ----------------
__global__ void zero_hist_k() {
    int i = blockIdx.x*256 + threadIdx.x;
    if (i < 2*NBUCK) g_hist[i] = 0;
}

__global__ void zero_f_k(float* p, int n) {
    int i = blockIdx.x*256 + threadIdx.x;
    if (i < n) p[i] = 0.f;
}

__device__ __forceinline__ int bucket_of(float d) {
    int b = (int)(d * (512.0f/30.0f));
    return min(max(b, 0), NBUCK-1);
}

__global__ void hist_k(const float* __restrict__ dist, int E) {
    int e = blockIdx.x*256 + threadIdx.x;
    if (e < E) atomicAdd(&g_hist[bucket_of(dist[e])], 1);
}

__global__ void scan512_k() {
    __shared__ int s[NBUCK];
    int tid = threadIdx.x;
    int v0 = g_hist[tid];
    s[tid] = v0;
    __syncthreads();
    for (int off = 1; off < NBUCK; off <<= 1) {
        int v = 0;
        if (tid >= off) v = s[tid - off];
        __syncthreads();
        s[tid] += v;
        __syncthreads();
    }
    g_hist[NBUCK + tid] = s[tid] - v0;   // exclusive prefix
}

__global__ void scatter_perm_k(const float* __restrict__ dist, int E) {
    int e = blockIdx.x*256 + threadIdx.x;
    if (e < E) {
        int b = bucket_of(dist[e]);
        int pos = atomicAdd(&g_hist[NBUCK + b], 1);
        g_perm[pos] = e;
    }
}

__global__ void init_h_k(const int* __restrict__ Z, const float* __restrict__ node_emb,
                         float* __restrict__ h, int N) {
    int idx = blockIdx.x*256 + threadIdx.x;
    if (idx < N*128) {
        int n = idx >> 7, d = idx & 127;
        h[idx] = node_emb[Z[n]*128 + d];
    }
}

// dst[k*J + j] = src[j*ldsrc + off + k]
__global__ void transpose_off_k(const float* __restrict__ src, float* __restrict__ dst,
                                int J, int Kd, int ldsrc, int off) {
    int idx = blockIdx.x*256 + threadIdx.x;
    if (idx < J*Kd) {
        int k = idx / J, j = idx % J;
        dst[(size_t)k*J + j] = src[(size_t)j*ldsrc + off + k];
    }
}

// P[layer][type][j] = be1[layer][j] + sum_k edge_emb[type][k] * We1[layer][j][k]
__global__ void p_kernel(const float* __restrict__ edge_emb, const float* __restrict__ We1,
                         const float* __restrict__ be1, float* __restrict__ P) {
    int ty = blockIdx.x, layer = blockIdx.y, j = threadIdx.x;
    __shared__ float em[128];
    if (j < 128) em[j] = edge_emb[ty*128 + j];
    __syncthreads();
    if (j < 428) {
        const float* wrow = We1 + ((size_t)layer*428 + j)*428;
        float acc = be1[layer*428 + j];
        #pragma unroll 8
        for (int k = 0; k < 128; k++) acc = fmaf(em[k], wrow[k], acc);
        P[((size_t)layer*400 + ty)*428 + j] = acc;
    }
}

// ---------------- windowed RBF GEMM: t = relu(rbf(dist) @ W1T + P[etype]) ----------------
// grid: (ceil(E/128), 4), 256 threads. Edges in perm (dist-sorted) order.
__global__ void __launch_bounds__(256, 2)
t_kernel(const float* __restrict__ dist, const int* __restrict__ etype,
         const int* __restrict__ perm, const float* __restrict__ W1T,
         const float* __restrict__ P, float* __restrict__ T, int E) {
    __shared__ __align__(16) float As[8][128];
    __shared__ __align__(16) float Bs[8][128];
    __shared__ float sd[128];
    __shared__ int   sty[128];
    __shared__ float rmn[128], rmx[128];

    int tid = threadIdx.x, bx = blockIdx.x, by = blockIdx.y;
    if (tid < 128) {
        int r = bx*128 + tid;
        int rr = (r < E) ? r : (E - 1);
        int e = perm[rr];
        float d = dist[e];
        sd[tid] = d; sty[tid] = etype[e];
        rmn[tid] = d; rmx[tid] = d;
    }
    __syncthreads();
    for (int s = 64; s > 0; s >>= 1) {
        if (tid < s) {
            rmn[tid] = fminf(rmn[tid], rmn[tid+s]);
            rmx[tid] = fmaxf(rmx[tid], rmx[tid+s]);
        }
        __syncthreads();
    }
    float dmn = rmn[0], dmx = rmx[0];
    int klo = (int)ceilf((dmn - WIN) * RBF_INV); if (klo < 0) klo = 0;
    int khi = (int)floorf((dmx + WIN) * RBF_INV); if (khi > N_RBF-1) khi = N_RBF-1;

    int trow = tid >> 4, tcol = tid & 15;
    int a_row = tid >> 1, a_kg = (tid & 1) * 4;
    int b_k = tid >> 5,  b_c = (tid & 31) * 4;
    float dA = sd[a_row];
    int colg0 = by * 128;

    float acc[8][8];
    #pragma unroll
    for (int i = 0; i < 8; i++)
        #pragma unroll
        for (int j = 0; j < 8; j++) acc[i][j] = 0.f;

    for (int k0 = klo; k0 <= khi; k0 += 8) {
        float av[4];
        #pragma unroll
        for (int i = 0; i < 4; i++) {
            int k = k0 + a_kg + i;
            float diff = dA - (float)k * RBF_STEP;
            av[i] = (k < N_RBF) ? __expf(-diff*diff*RBF_INV) : 0.f;
        }
        float4 bv = make_float4(0.f, 0.f, 0.f, 0.f);
        {
            int k = k0 + b_k;
            int cg = colg0 + b_c;
            if (k < N_RBF) {
                const float* Bp = W1T + (size_t)k*428 + cg;
                if (cg + 3 < 428) bv = *(const float4*)Bp;
                else {
                    if (cg + 0 < 428) bv.x = Bp[0];
                    if (cg + 1 < 428) bv.y = Bp[1];
                    if (cg + 2 < 428) bv.z = Bp[2];
                }
            }
        }
        __syncthreads();
        #pragma unroll
        for (int i = 0; i < 4; i++) As[a_kg + i][a_row] = av[i];
        *(float4*)&Bs[b_k][b_c] = bv;
        __syncthreads();
        #pragma unroll
        for (int kk = 0; kk < 8; kk++) {
            float a[8], b[8];
            *(float4*)&a[0] = *(const float4*)&As[kk][trow*8];
            *(float4*)&a[4] = *(const float4*)&As[kk][trow*8 + 4];
            *(float4*)&b[0] = *(const float4*)&Bs[kk][tcol*8];
            *(float4*)&b[4] = *(const float4*)&Bs[kk][tcol*8 + 4];
            #pragma unroll
            for (int i = 0; i < 8; i++)
                #pragma unroll
                for (int j = 0; j < 8; j++)
                    acc[i][j] = fmaf(a[i], b[j], acc[i][j]);
        }
    }

    #pragma unroll
    for (int i = 0; i < 8; i++) {
        int row = bx*128 + trow*8 + i;
        if (row < E) {
            int ety = sty[trow*8 + i];
            const float* Pr = P + (size_t)ety * 428;
            size_t tb = (size_t)row * 428;
            #pragma unroll
            for (int jj = 0; jj < 8; jj += 4) {
                int col = colg0 + tcol*8 + jj;
                if (col + 3 < 428) {
                    float4 pv = *(const float4*)(Pr + col);
                    float4 o;
                    o.x = fmaxf(acc[i][jj+0] + pv.x, 0.f);
                    o.y = fmaxf(acc[i][jj+1] + pv.y, 0.f);
                    o.z = fmaxf(acc[i][jj+2] + pv.z, 0.f);
                    o.w = fmaxf(acc[i][jj+3] + pv.w, 0.f);
                    *(float4*)(T + tb + col) = o;
                } else {
                    #pragma unroll
                    for (int q = 0; q < 4; q++) {
                        int c = col + q;
                        if (c < 428) T[tb + c] = fmaxf(acc[i][jj+q] + Pr[c], 0.f);
                    }
                }
            }
        }
    }
}

// ---------------- generic 128-N GEMM: C[M,128] = epi(A[M,K] @ B[K,128] + bias) ----------------
// EPI: 0 = store, 1 = relu store, 2 = (acc+bias)*EE store, 3 = tanh + atomicAdd scatter to Hout[dst]
// GATHER: A row index = gidx[perm[row]]
template<int EPI, bool GATHER>
__global__ void __launch_bounds__(256, 2)
gemm128(const float* A, const float* __restrict__ B,
        const float* __restrict__ bias, float* C,
        int M, int K,
        const int* __restrict__ perm, const int* __restrict__ gidx,
        const float* __restrict__ EE, float* Hout) {
    __shared__ __align__(16) float As[8][128];
    __shared__ __align__(16) float Bs[8][128];
    __shared__ float sbias[128];

    int tid = threadIdx.x, bx = blockIdx.x;
    if (tid < 128) sbias[tid] = bias[tid];

    int trow = tid >> 4, tcol = tid & 15;
    int a_row = tid >> 1, a_kg = (tid & 1) * 4;
    int b_k = tid >> 5,  b_c = (tid & 31) * 4;

    int gr = bx*128 + a_row;
    bool arow_valid = (gr < M);
    const float* Arow = A;
    if (arow_valid) {
        int ar = GATHER ? gidx[perm[gr]] : gr;
        Arow = A + (size_t)ar * K;
    }

    float acc[8][8];
    #pragma unroll
    for (int i = 0; i < 8; i++)
        #pragma unroll
        for (int j = 0; j < 8; j++) acc[i][j] = 0.f;

    for (int k0 = 0; k0 < K; k0 += 8) {
        float4 av = make_float4(0.f, 0.f, 0.f, 0.f);
        if (arow_valid) {
            int k = k0 + a_kg;
            if (k + 3 < K) av = *(const float4*)(Arow + k);
            else {
                if (k + 0 < K) av.x = Arow[k + 0];
                if (k + 1 < K) av.y = Arow[k + 1];
                if (k + 2 < K) av.z = Arow[k + 2];
                if (k + 3 < K) av.w = Arow[k + 3];
            }
        }
        float4 bv = make_float4(0.f, 0.f, 0.f, 0.f);
        {
            int k = k0 + b_k;
            if (k < K) bv = *(const float4*)(B + (size_t)k*128 + b_c);
        }
        __syncthreads();
        As[a_kg + 0][a_row] = av.x;
        As[a_kg + 1][a_row] = av.y;
        As[a_kg + 2][a_row] = av.z;
        As[a_kg + 3][a_row] = av.w;
        *(float4*)&Bs[b_k][b_c] = bv;
        __syncthreads();
        #pragma unroll
        for (int kk = 0; kk < 8; kk++) {
            float a[8], b[8];
            *(float4*)&a[0] = *(const float4*)&As[kk][trow*8];
            *(float4*)&a[4] = *(const float4*)&As[kk][trow*8 + 4];
            *(float4*)&b[0] = *(const float4*)&Bs[kk][tcol*8];
            *(float4*)&b[4] = *(const float4*)&Bs[kk][tcol*8 + 4];
            #pragma unroll
            for (int i = 0; i < 8; i++)
                #pragma unroll
                for (int j = 0; j < 8; j++)
                    acc[i][j] = fmaf(a[i], b[j], acc[i][j]);
        }
    }

    #pragma unroll
    for (int i = 0; i < 8; i++) {
        int row = bx*128 + trow*8 + i;
        if (row < M) {
            if (EPI == 3) {
                int dg = gidx[perm[row]];
                float* Hr = Hout + (size_t)dg * 128 + tcol*8;
                #pragma unroll
                for (int j = 0; j < 8; j++) {
                    float v = tanhf(acc[i][j] + sbias[tcol*8 + j]);
                    atomicAdd(&Hr[j], v);
                }
            } else {
                size_t base = (size_t)row * 128 + tcol*8;
                #pragma unroll
                for (int jj = 0; jj < 8; jj += 4) {
                    float4 o;
                    float v0 = acc[i][jj+0] + sbias[tcol*8 + jj+0];
                    float v1 = acc[i][jj+1] + sbias[tcol*8 + jj+1];
                    float v2 = acc[i][jj+2] + sbias[tcol*8 + jj+2];
                    float v3 = acc[i][jj+3] + sbias[tcol*8 + jj+3];
                    if (EPI == 1) {
                        v0 = fmaxf(v0, 0.f); v1 = fmaxf(v1, 0.f);
                        v2 = fmaxf(v2, 0.f); v3 = fmaxf(v3, 0.f);
                    }
                    if (EPI == 2) {
                        float4 e4 = *(const float4*)(EE + base + jj);
                        v0 *= e4.x; v1 *= e4.y; v2 *= e4.z; v3 *= e4.w;
                    }
                    o.x = v0; o.y = v1; o.z = v2; o.w = v3;
                    *(float4*)(C + base + jj) = o;
                }
            }
        }
    }
}

// ---------------- readout: r[n] = dot(rr1[n], Wr2) + br2; out[gid[n]] += r ----------------
__global__ void readout2_k(const float* __restrict__ rr, const float* __restrict__ Wr2,
                           const float* __restrict__ br2, const int* __restrict__ gid,
                           float* __restrict__ out, int N) {
    __shared__ float w[128];
    int tid = threadIdx.x;
    if (tid < 128) w[tid] = Wr2[tid];
    __syncthreads();
    int warp = tid >> 5, lane = tid & 31;
    int n = blockIdx.x*4 + warp;
    if (n >= N) return;
    const float* hr = rr + (size_t)n * 128;
    float s = 0.f;
    #pragma unroll
    for (int i = 0; i < 4; i++) s = fmaf(hr[lane + i*32], w[lane + i*32], s);
    #pragma unroll
    for (int o = 16; o > 0; o >>= 1) s += __shfl_down_sync(0xffffffffu, s, o);
    if (lane == 0) atomicAdd(&out[gid[n]], s + br2[0]);
}

// ---------------- launch ----------------
extern "C" void kernel_launch(void* const* d_in, const int* in_sizes, int n_in,
                              void* d_out, int out_size) {
    const int*   Z        = (const int*)  d_in[0];
    const int*   etype    = (const int*)  d_in[1];
    const float* dist     = (const float*)d_in[2];
    const int*   src      = (const int*)  d_in[3];
    const int*   dst      = (const int*)  d_in[4];
    const int*   gid      = (const int*)  d_in[5];
    const float* node_emb = (const float*)d_in[6];
    const float* edge_emb = (const float*)d_in[7];
    const float* Wn1 = (const float*)d_in[8];
    const float* bn1 = (const float*)d_in[9];
    const float* Wn2 = (const float*)d_in[10];
    const float* bn2 = (const float*)d_in[11];
    const float* We1 = (const float*)d_in[12];
    const float* be1 = (const float*)d_in[13];
    const float* We2 = (const float*)d_in[14];
    const float* be2 = (const float*)d_in[15];
    const float* Wc  = (const float*)d_in[16];
    const float* bc  = (const float*)d_in[17];
    const float* Wr1 = (const float*)d_in[18];
    const float* br1 = (const float*)d_in[19];
    const float* Wr2 = (const float*)d_in[20];
    const float* br2 = (const float*)d_in[21];

    int N = in_sizes[0];
    int E = in_sizes[1];
    int G = out_size;
    float* out = (float*)d_out;

    void* p;
    float *h, *t, *ee, *tmp, *W1T, *We2T, *Wn1T, *Wn2T, *WcT, *Wr1T, *P;
    int *perm;
    cudaGetSymbolAddress(&p, g_h);    h    = (float*)p;
    cudaGetSymbolAddress(&p, g_t);    t    = (float*)p;
    cudaGetSymbolAddress(&p, g_ee);   ee   = (float*)p;
    cudaGetSymbolAddress(&p, g_tmp);  tmp  = (float*)p;
    cudaGetSymbolAddress(&p, g_W1T);  W1T  = (float*)p;
    cudaGetSymbolAddress(&p, g_We2T); We2T = (float*)p;
    cudaGetSymbolAddress(&p, g_Wn1T); Wn1T = (float*)p;
    cudaGetSymbolAddress(&p, g_Wn2T); Wn2T = (float*)p;
    cudaGetSymbolAddress(&p, g_WcT);  WcT  = (float*)p;
    cudaGetSymbolAddress(&p, g_Wr1T); Wr1T = (float*)p;
    cudaGetSymbolAddress(&p, g_P);    P    = (float*)p;
    cudaGetSymbolAddress(&p, g_perm); perm = (int*)p;

    // counting sort of edges by dist (for windowed RBF GEMM)
    zero_hist_k<<<(2*NBUCK + 255)/256, 256>>>();
    hist_k<<<(E + 255)/256, 256>>>(dist, E);
    scan512_k<<<1, NBUCK>>>();
    scatter_perm_k<<<(E + 255)/256, 256>>>(dist, E);

    // h init + weight transposes + P precompute
    init_h_k<<<(N*128 + 255)/256, 256>>>(Z, node_emb, h, N);
    for (int i = 0; i < 3; i++) {
        transpose_off_k<<<(428*300 + 255)/256, 256>>>(We1 + (size_t)i*428*428, W1T + (size_t)i*300*428, 428, 300, 428, 128);
        transpose_off_k<<<(128*428 + 255)/256, 256>>>(We2 + (size_t)i*128*428, We2T + (size_t)i*428*128, 128, 428, 428, 0);
        transpose_off_k<<<(128*128 + 255)/256, 256>>>(Wn1 + (size_t)i*128*128, Wn1T + (size_t)i*128*128, 128, 128, 128, 0);
        transpose_off_k<<<(128*128 + 255)/256, 256>>>(Wn2 + (size_t)i*128*128, Wn2T + (size_t)i*128*128, 128, 128, 128, 0);
        transpose_off_k<<<(128*128 + 255)/256, 256>>>(Wc  + (size_t)i*128*128, WcT  + (size_t)i*128*128, 128, 128, 128, 0);
    }
    transpose_off_k<<<(128*128 + 255)/256, 256>>>(Wr1, Wr1T, 128, 128, 128, 0);
    p_kernel<<<dim3(400, 3), 448>>>(edge_emb, We1, be1, P);

    int gE = (E + 127)/128;
    for (int i = 0; i < 3; i++) {
        // t = relu(e @ We1^T + be1)   (windowed RBF GEMM + P table)
        t_kernel<<<dim3(gE, 4), 256>>>(dist, etype, perm,
                                       W1T + (size_t)i*300*428,
                                       P + (size_t)i*400*428, t, E);
        // ee = t @ We2^T + be2
        gemm128<0, false><<<gE, 256>>>(t, We2T + (size_t)i*428*128, be2 + i*128,
                                       ee, E, 428, nullptr, nullptr, nullptr, nullptr);
        // tmp = relu(h[src] @ Wn1^T + bn1)
        gemm128<1, true><<<gE, 256>>>(h, Wn1T + (size_t)i*128*128, bn1 + i*128,
                                      tmp, E, 128, perm, src, nullptr, nullptr);
        // tmp = (tmp @ Wn2^T + bn2) * ee     (in-place safe: block-row exclusive)
        gemm128<2, false><<<gE, 256>>>(tmp, Wn2T + (size_t)i*128*128, bn2 + i*128,
                                       tmp, E, 128, nullptr, nullptr, ee, nullptr);
        // h[dst] += tanh(tmp @ Wc^T + bc)
        gemm128<3, false><<<gE, 256>>>(tmp, WcT + (size_t)i*128*128, bc + i*128,
                                       nullptr, E, 128, perm, dst, nullptr, h);
    }

    // readout
    gemm128<1, false><<<(N + 127)/128, 256>>>(h, Wr1T, br1, tmp, N, 128,
                                              nullptr, nullptr, nullptr, nullptr);
    zero_f_k<<<(G + 255)/256, 256>>>(out, G);
    readout2_k<<<(N + 3)/4, 128>>>(tmp, Wr2, br2, gid, out, N);
}